// round 2
// baseline (speedup 1.0000x reference)
#include <cuda_runtime.h>

#define BB 16
#define HH 384
#define WW 384
#define HO 382
#define WO 382
#define RPAD 5
#define TH (8 + 2 + 2*RPAD)    /* 20 */
#define TW (32 + 2 + 2*RPAD)   /* 44 */

typedef unsigned long long u64;

// Packed f32x2 FMA (FFMA2) — 2x fp32 throughput on sm_103a, PTX-only.
__device__ __forceinline__ u64 ffma2(u64 a, u64 b, u64 c){
    u64 d; asm("fma.rn.f32x2 %0,%1,%2,%3;" : "=l"(d) : "l"(a), "l"(b), "l"(c)); return d;
}
__device__ __forceinline__ u64 rep2(float x){
    u64 r; asm("mov.b64 %0,{%1,%1};" : "=l"(r) : "f"(x)); return r;
}
__device__ __forceinline__ float2 unpack2(u64 v){
    float2 f; asm("mov.b64 {%0,%1},%2;" : "=f"(f.x), "=f"(f.y) : "l"(v)); return f;
}

// Fused offset-conv + deformable conv. Block = 32x8 output tile.
// All x reads (conv taps AND bilinear gathers) come from a block-staged
// planar smem tile with RPAD halo; rare out-of-window samples fall back
// to global LDG for correctness on arbitrary offsets.
__global__ __launch_bounds__(256) void dcn_fused(
    const float* __restrict__ x,
    const float* __restrict__ conv_w,
    const float* __restrict__ conv_b,
    const float* __restrict__ dcn_w,
    const float* __restrict__ dcn_b,
    float* __restrict__ out)
{
    __shared__ float tile[3][TH][TW];                  // 10,560 B
    __shared__ __align__(16) float cwp[27 * 20];       // conv weights, (dy,dx) pair-packed
    __shared__ __align__(16) float cbs[20];
    __shared__ __align__(16) float dws[84];
    __shared__ __align__(16) float dbs[4];

    int tid = threadIdx.y * 32 + threadIdx.x;
    for (int idx = tid; idx < 486; idx += 256) {
        int o = idx / 27, jj = idx % 27;
        cwp[jj * 20 + o] = conv_w[idx];
    }
    if (tid < 18) cbs[tid] = conv_b[tid];
    if (tid < 81) dws[tid] = dcn_w[tid];
    if (tid < 3)  dbs[tid] = dcn_b[tid];

    int i0 = blockIdx.y * 8;
    int j0 = blockIdx.x * 32;
    int b  = blockIdx.z;
    int ybase = i0 - RPAD;
    int xbase = j0 - RPAD;

    const float* p0 = x + (size_t)b * 3 * HH * WW;
    const float* p1 = p0 + HH * WW;
    const float* p2 = p1 + HH * WW;

    // ---- Stage input tile (clamped at image borders, coalesced along x) ----
    for (int idx = tid; idx < TH * TW; idx += 256) {
        int r = idx / TW, q = idx % TW;
        int gy = min(max(ybase + r, 0), HH - 1);
        int gx = min(max(xbase + q, 0), WW - 1);
        int g = gy * WW + gx;
        tile[0][r][q] = p0[g];
        tile[1][r][q] = p1[g];
        tile[2][r][q] = p2[g];
    }
    __syncthreads();

    int j = j0 + threadIdx.x;
    int i = i0 + threadIdx.y;
    if (i >= HO || j >= WO) return;

    // ---- Offset conv from smem: 9 f32x2 accumulators = (dy_k, dx_k) ----
    u64 off2[9];
    const u64* cb2 = (const u64*)cbs;
    #pragma unroll
    for (int p = 0; p < 9; p++) off2[p] = cb2[p];

    int ly = threadIdx.y + RPAD;   // local coord of output pixel's top-left tap
    int lx = threadIdx.x + RPAD;
    #pragma unroll
    for (int c = 0; c < 3; c++) {
        #pragma unroll
        for (int ky = 0; ky < 3; ky++) {
            #pragma unroll
            for (int kx = 0; kx < 3; kx++) {
                u64 xv2 = rep2(tile[c][ly + ky][lx + kx]);
                const u64* wrow = (const u64*)&cwp[(c * 9 + ky * 3 + kx) * 20];
                #pragma unroll
                for (int p = 0; p < 9; p++)
                    off2[p] = ffma2(xv2, wrow[p], off2[p]);
            }
        }
    }

    // ---- Deformable sampling (smem fast path) + 3-channel einsum ----
    float fi = (float)i, fj = (float)j;
    float acc0 = dbs[0], acc1 = dbs[1], acc2 = dbs[2];

    #pragma unroll
    for (int k = 0; k < 9; k++) {
        int ky = k / 3, kx = k % 3;
        float2 od = unpack2(off2[k]);            // (dy, dx)
        float py = od.x + (fi + (float)ky);
        float px = od.y + (fj + (float)kx);
        float y0f = floorf(py), x0f = floorf(px);
        float wy = py - y0f,   wx = px - x0f;
        int y0 = (int)y0f, x0 = (int)x0f;
        int y1 = y0 + 1,   x1 = x0 + 1;
        float vy0 = ((unsigned)y0 < (unsigned)HH) ? 1.f : 0.f;
        float vy1 = ((unsigned)y1 < (unsigned)HH) ? 1.f : 0.f;
        float vx0 = ((unsigned)x0 < (unsigned)WW) ? 1.f : 0.f;
        float vx1 = ((unsigned)x1 < (unsigned)WW) ? 1.f : 0.f;
        int yc0 = min(max(y0, 0), HH - 1), yc1 = min(max(y1, 0), HH - 1);
        int xc0 = min(max(x0, 0), WW - 1), xc1 = min(max(x1, 0), WW - 1);

        float a0 = (1.f - wy) * vy0, a1 = wy * vy1;
        float b0 = (1.f - wx) * vx0, b1 = wx * vx1;
        float w00 = a0 * b0, w01 = a0 * b1, w10 = a1 * b0, w11 = a1 * b1;

        // tile-local coords of the (clamped) corners
        int ry0 = yc0 - ybase, ry1 = yc1 - ybase;
        int rx0 = xc0 - xbase, rx1 = xc1 - xbase;
        bool inw = ((unsigned)ry0 < (unsigned)TH) & ((unsigned)ry1 < (unsigned)TH) &
                   ((unsigned)rx0 < (unsigned)TW) & ((unsigned)rx1 < (unsigned)TW);

        if (__builtin_expect(inw, 1)) {
            #pragma unroll
            for (int c = 0; c < 3; c++) {
                float g00 = tile[c][ry0][rx0], g01 = tile[c][ry0][rx1];
                float g10 = tile[c][ry1][rx0], g11 = tile[c][ry1][rx1];
                float val = fmaf(g11, w11, fmaf(g10, w10, fmaf(g01, w01, g00 * w00)));
                acc0 = fmaf(val, dws[ 0 + c * 9 + k], acc0);
                acc1 = fmaf(val, dws[27 + c * 9 + k], acc1);
                acc2 = fmaf(val, dws[54 + c * 9 + k], acc2);
            }
        } else {
            int i00 = yc0 * WW + xc0, i01 = yc0 * WW + xc1;
            int i10 = yc1 * WW + xc0, i11 = yc1 * WW + xc1;
            const float* pcs[3] = {p0, p1, p2};
            #pragma unroll
            for (int c = 0; c < 3; c++) {
                const float* pc = pcs[c];
                float g00 = __ldg(pc + i00), g01 = __ldg(pc + i01);
                float g10 = __ldg(pc + i10), g11 = __ldg(pc + i11);
                float val = fmaf(g11, w11, fmaf(g10, w10, fmaf(g01, w01, g00 * w00)));
                acc0 = fmaf(val, dws[ 0 + c * 9 + k], acc0);
                acc1 = fmaf(val, dws[27 + c * 9 + k], acc1);
                acc2 = fmaf(val, dws[54 + c * 9 + k], acc2);
            }
        }
    }

    size_t ob = (size_t)b * 3 * HO * WO + (size_t)i * WO + j;
    out[ob]                       = acc0;
    out[ob + (size_t)HO * WO]     = acc1;
    out[ob + 2 * (size_t)HO * WO] = acc2;
}

extern "C" void kernel_launch(void* const* d_in, const int* in_sizes, int n_in,
                              void* d_out, int out_size)
{
    const float* x      = (const float*)d_in[0];
    const float* conv_w = (const float*)d_in[1];
    const float* conv_b = (const float*)d_in[2];
    const float* dcn_w  = (const float*)d_in[3];
    const float* dcn_b  = (const float*)d_in[4];
    float* out = (float*)d_out;

    dim3 blk(32, 8);
    dim3 grd((WO + 31) / 32, (HO + 7) / 8, BB);
    dcn_fused<<<grd, blk>>>(x, conv_w, conv_b, dcn_w, dcn_b, out);
}

// round 3
// speedup vs baseline: 1.5301x; 1.5301x over previous
#include <cuda_runtime.h>

#define HH 384
#define WW 384
#define HO 382
#define WO 382
#define RPAD 5
#define TH 20
#define TW 44

typedef unsigned long long u64;

// Constant layout (floats):
// [0,540)   cwp[27][20]: conv weight pairs, cwp[j*20+2p] = (w[2p][j], w[2p+1][j])
// [540,558) cb pairs: (bias[2p], bias[2p+1])
// [560,614) dwp[27] u64 pairs: (dcn_w[o][0][k], dcn_w[o][1][k]) at 560+(o*9+k)*2
// [614,641) dw2: dcn_w[o][2][k] at 614+o*9+k
// [641,644) db[3]
__constant__ __align__(16) float CW[644];
__device__ __align__(16) float d_scratch[644];

__device__ __forceinline__ u64 ffma2(u64 a, u64 b, u64 c){
    u64 d; asm("fma.rn.f32x2 %0,%1,%2,%3;" : "=l"(d) : "l"(a), "l"(b), "l"(c)); return d;
}
__device__ __forceinline__ u64 mul2(u64 a, u64 b){
    u64 d; asm("mul.rn.f32x2 %0,%1,%2;" : "=l"(d) : "l"(a), "l"(b)); return d;
}
__device__ __forceinline__ u64 rep2(float x){
    u64 r; asm("mov.b64 %0,{%1,%1};" : "=l"(r) : "f"(x)); return r;
}
__device__ __forceinline__ u64 pack2(float a, float b){
    u64 r; asm("mov.b64 %0,{%1,%2};" : "=l"(r) : "f"(a), "f"(b)); return r;
}
__device__ __forceinline__ float2 unpack2(u64 v){
    float2 f; asm("mov.b64 {%0,%1},%2;" : "=f"(f.x), "=f"(f.y) : "l"(v)); return f;
}
__device__ __forceinline__ u64 ldc64(int foff){   // foff compile-time, 8B-aligned
    return *reinterpret_cast<const u64*>(&CW[foff]);
}

// Repack raw weights into the constant-image layout (written to d_scratch,
// then memcpy'd into CW before the main kernel).
__global__ void repack(const float* __restrict__ cw, const float* __restrict__ cb,
                       const float* __restrict__ dw, const float* __restrict__ db,
                       float* __restrict__ s)
{
    int t = threadIdx.x;
    if (t < 486) { int o = t / 27, j = t % 27; s[j * 20 + o] = cw[t]; }
    else if (t < 504) { s[540 + (t - 486)] = cb[t - 486]; }
    else if (t < 531) {
        int i = t - 504; int o = i / 9, k = i % 9;
        s[560 + i * 2 + 0] = dw[o * 27 + 0 + k];
        s[560 + i * 2 + 1] = dw[o * 27 + 9 + k];
        s[614 + i]         = dw[o * 27 + 18 + k];
    }
    else if (t < 534) { s[641 + (t - 531)] = db[t - 531]; }
}

// Fused offset-conv + deformable conv. Block = 32x8 output tile.
// Channel-interleaved float4 smem tile: one LDS.128 = all 3 channels of a
// tap/corner. All weights come from __constant__ (constant port, off L1tex).
__global__ __launch_bounds__(256) void dcn_fused(
    const float* __restrict__ x, float* __restrict__ out)
{
    __shared__ float4 tile[TH][TW];   // 14,080 B

    int tid = threadIdx.y * 32 + threadIdx.x;
    int i0 = blockIdx.y * 8, j0 = blockIdx.x * 32, b = blockIdx.z;
    int ybase = i0 - RPAD, xbase = j0 - RPAD;

    const float* p0 = x + (size_t)b * 3 * HH * WW;
    const float* p1 = p0 + HH * WW;
    const float* p2 = p1 + HH * WW;

    // ---- Stage channel-interleaved tile (border-clamped, x-coalesced) ----
    #pragma unroll
    for (int it = 0; it < 4; it++) {
        int idx = tid + it * 256;
        if (idx < TH * TW) {
            int r = idx / TW, q = idx % TW;
            int gy = min(max(ybase + r, 0), HH - 1);
            int gx = min(max(xbase + q, 0), WW - 1);
            int g = gy * WW + gx;
            tile[r][q] = make_float4(__ldg(p0 + g), __ldg(p1 + g), __ldg(p2 + g), 0.f);
        }
    }
    __syncthreads();

    int j = j0 + threadIdx.x;
    int i = i0 + threadIdx.y;
    if (i >= HO || j >= WO) return;

    // ---- Offset conv: 9 f32x2 accumulators = (dy_k, dx_k), weights from CW ----
    u64 off2[9];
    #pragma unroll
    for (int p = 0; p < 9; p++) off2[p] = ldc64(540 + 2 * p);

    int ly = threadIdx.y + RPAD, lx = threadIdx.x + RPAD;
    #pragma unroll
    for (int ky = 0; ky < 3; ky++) {
        #pragma unroll
        for (int kx = 0; kx < 3; kx++) {
            float4 v = tile[ly + ky][lx + kx];
            #pragma unroll
            for (int c = 0; c < 3; c++) {
                float xc = (c == 0) ? v.x : (c == 1) ? v.y : v.z;
                u64 xv2 = rep2(xc);
                const int jj = c * 9 + ky * 3 + kx;
                #pragma unroll
                for (int p = 0; p < 9; p++)
                    off2[p] = ffma2(xv2, ldc64(jj * 20 + 2 * p), off2[p]);
            }
        }
    }

    // ---- Deformable sampling + einsum (c0,c1 packed f32x2; c2 scalar) ----
    float fi = (float)i, fj = (float)j;
    u64 accP[3];
    float acc2s[3];
    #pragma unroll
    for (int o = 0; o < 3; o++) { accP[o] = 0ULL; acc2s[o] = CW[641 + o]; }

    #pragma unroll
    for (int k = 0; k < 9; k++) {
        const int ky = k / 3, kx = k % 3;
        float2 od = unpack2(off2[k]);            // (dy, dx)
        float py = od.x + (fi + (float)ky);
        float px = od.y + (fj + (float)kx);
        int y0 = __float2int_rd(py), x0 = __float2int_rd(px);
        float wy = py - (float)y0, wx = px - (float)x0;
        int y1 = y0 + 1, x1 = x0 + 1;
        float vy0 = ((unsigned)y0 < (unsigned)HH) ? 1.f : 0.f;
        float vy1 = ((unsigned)y1 < (unsigned)HH) ? 1.f : 0.f;
        float vx0 = ((unsigned)x0 < (unsigned)WW) ? 1.f : 0.f;
        float vx1 = ((unsigned)x1 < (unsigned)WW) ? 1.f : 0.f;
        int yc0 = min(max(y0, 0), HH - 1), yc1 = min(max(y1, 0), HH - 1);
        int xc0 = min(max(x0, 0), WW - 1), xc1 = min(max(x1, 0), WW - 1);

        float a0 = (1.f - wy) * vy0, a1 = wy * vy1;
        float b0 = (1.f - wx) * vx0, b1 = wx * vx1;
        float w00 = a0 * b0, w01 = a0 * b1, w10 = a1 * b0, w11 = a1 * b1;

        int ry0 = yc0 - ybase, ry1 = yc1 - ybase;
        int rx0 = xc0 - xbase, rx1 = xc1 - xbase;
        bool inw = ((unsigned)ry0 < (unsigned)TH) & ((unsigned)ry1 < (unsigned)TH) &
                   ((unsigned)rx0 < (unsigned)TW) & ((unsigned)rx1 < (unsigned)TW);

        float4 g00, g01, g10, g11;
        if (__builtin_expect(inw, 1)) {
            g00 = tile[ry0][rx0]; g01 = tile[ry0][rx1];
            g10 = tile[ry1][rx0]; g11 = tile[ry1][rx1];
        } else {
            int i00 = yc0 * WW + xc0, i01 = yc0 * WW + xc1;
            int i10 = yc1 * WW + xc0, i11 = yc1 * WW + xc1;
            g00 = make_float4(__ldg(p0 + i00), __ldg(p1 + i00), __ldg(p2 + i00), 0.f);
            g01 = make_float4(__ldg(p0 + i01), __ldg(p1 + i01), __ldg(p2 + i01), 0.f);
            g10 = make_float4(__ldg(p0 + i10), __ldg(p1 + i10), __ldg(p2 + i10), 0.f);
            g11 = make_float4(__ldg(p0 + i11), __ldg(p1 + i11), __ldg(p2 + i11), 0.f);
        }

        // bilinear for (c0,c1) packed, c2 scalar
        u64 v01 = mul2(pack2(g00.x, g00.y), rep2(w00));
        v01 = ffma2(pack2(g01.x, g01.y), rep2(w01), v01);
        v01 = ffma2(pack2(g10.x, g10.y), rep2(w10), v01);
        v01 = ffma2(pack2(g11.x, g11.y), rep2(w11), v01);
        float v2 = fmaf(g11.z, w11, fmaf(g10.z, w10, fmaf(g01.z, w01, g00.z * w00)));

        #pragma unroll
        for (int o = 0; o < 3; o++) {
            accP[o]  = ffma2(v01, ldc64(560 + (o * 9 + k) * 2), accP[o]);
            acc2s[o] = fmaf(v2, CW[614 + o * 9 + k], acc2s[o]);
        }
    }

    size_t ob = (size_t)b * 3 * HO * WO + (size_t)i * WO + j;
    #pragma unroll
    for (int o = 0; o < 3; o++) {
        float2 ap = unpack2(accP[o]);
        out[ob + (size_t)o * HO * WO] = ap.x + ap.y + acc2s[o];
    }
}

extern "C" void kernel_launch(void* const* d_in, const int* in_sizes, int n_in,
                              void* d_out, int out_size)
{
    const float* x      = (const float*)d_in[0];
    const float* conv_w = (const float*)d_in[1];
    const float* conv_b = (const float*)d_in[2];
    const float* dcn_w  = (const float*)d_in[3];
    const float* dcn_b  = (const float*)d_in[4];
    float* out = (float*)d_out;

    float* sp = nullptr;  void* cp = nullptr;
    cudaGetSymbolAddress((void**)&sp, d_scratch);
    cudaGetSymbolAddress(&cp, CW);

    repack<<<1, 544>>>(conv_w, conv_b, dcn_w, dcn_b, sp);
    cudaMemcpyAsync(cp, sp, 644 * sizeof(float), cudaMemcpyDeviceToDevice);

    dim3 blk(32, 8);
    dim3 grd((WO + 31) / 32, (HO + 7) / 8, 16);
    dcn_fused<<<grd, blk>>>(x, out);
}

// round 4
// speedup vs baseline: 1.6030x; 1.0476x over previous
#include <cuda_runtime.h>

#define HH 384
#define WW 384
#define HO 382
#define WO 382
#define RPAD 5
#define TH 20    /* 8 + 2 + 2*RPAD */
#define TW 44    /* 32 + 2 + 2*RPAD */

typedef unsigned long long u64;

// Constant layout (floats):
// [0,540)    cwp[27][20]: conv weight pairs, cwp[jj*20+2p] = (w[2p][jj], w[2p+1][jj])
// [540,558)  conv-bias pairs: (bias[2p], bias[2p+1]) at 540+2p
// [560,632)  dcn (c0,c1) pairs, padded: (dcn_w[o][0][k], dcn_w[o][1][k]) at 560+k*8+2o
// [632,659)  dcn c2: dcn_w[o][2][k] at 632+k*3+o
// [660,663)  dcn bias
__constant__ __align__(16) float CW[672];
__device__ __align__(16) float d_scratch[672];

__device__ __forceinline__ u64 ffma2(u64 a, u64 b, u64 c){
    u64 d; asm("fma.rn.f32x2 %0,%1,%2,%3;" : "=l"(d) : "l"(a), "l"(b), "l"(c)); return d;
}
__device__ __forceinline__ u64 mul2(u64 a, u64 b){
    u64 d; asm("mul.rn.f32x2 %0,%1,%2;" : "=l"(d) : "l"(a), "l"(b)); return d;
}
__device__ __forceinline__ u64 add2(u64 a, u64 b){
    u64 d; asm("add.rn.f32x2 %0,%1,%2;" : "=l"(d) : "l"(a), "l"(b)); return d;
}
__device__ __forceinline__ u64 rep2(float x){
    u64 r; asm("mov.b64 %0,{%1,%1};" : "=l"(r) : "f"(x)); return r;
}
__device__ __forceinline__ u64 pack2(float a, float b){
    u64 r; asm("mov.b64 %0,{%1,%2};" : "=l"(r) : "f"(a), "f"(b)); return r;
}
__device__ __forceinline__ float2 unpack2(u64 v){
    float2 f; asm("mov.b64 {%0,%1},%2;" : "=f"(f.x), "=f"(f.y) : "l"(v)); return f;
}
__device__ __forceinline__ u64 ldc64(int foff){
    return *reinterpret_cast<const u64*>(&CW[foff]);
}
__device__ __forceinline__ ulonglong2 ldc128(int foff){
    return *reinterpret_cast<const ulonglong2*>(&CW[foff]);
}

__global__ void repack(const float* __restrict__ cw, const float* __restrict__ cb,
                       const float* __restrict__ dw, const float* __restrict__ db,
                       float* __restrict__ s)
{
    int t = threadIdx.x;
    if (t < 486) { int o = t / 27, jj = t % 27; s[jj * 20 + o] = cw[t]; }
    else if (t < 504) { s[540 + (t - 486)] = cb[t - 486]; }
    else if (t < 531) {
        int i = t - 504; int o = i / 9, k = i % 9;
        s[560 + k * 8 + 2 * o + 0] = dw[o * 27 + 0 + k];
        s[560 + k * 8 + 2 * o + 1] = dw[o * 27 + 9 + k];
        s[632 + k * 3 + o]         = dw[o * 27 + 18 + k];
    }
    else if (t < 534) { s[660 + (t - 531)] = db[t - 531]; }
    else if (t < 543) { int k = t - 534; s[560 + k * 8 + 6] = 0.f; s[560 + k * 8 + 7] = 0.f; }
}

// Fused offset-conv + deformable conv. Block = 32x4 threads, each thread does
// 2 vertically adjacent pixels -> 32x8 output tile. Split smem tile:
// (c0,c1) as u64 + c2 scalar. Weights in __constant__, loaded once per thread.
__global__ __launch_bounds__(128, 4) void dcn_fused(
    const float* __restrict__ x, float* __restrict__ out)
{
    __shared__ u64   tileP[TH][TW];   // 7040 B
    __shared__ float tile2[TH][TW];   // 3520 B

    const int tx = threadIdx.x, ty = threadIdx.y;
    const int tid = ty * 32 + tx;
    const int i0 = blockIdx.y * 8, j0 = blockIdx.x * 32, b = blockIdx.z;
    const int ybase = i0 - RPAD, xbase = j0 - RPAD;

    const float* p0 = x + (size_t)b * 3 * HH * WW;
    const float* p1 = p0 + HH * WW;
    const float* p2 = p1 + HH * WW;

    // ---- Stage tile (border-clamped; clamp doubles as border handling later) ----
    #pragma unroll
    for (int it = 0; it < 7; it++) {
        int idx = tid + it * 128;
        if (idx < TH * TW) {
            int r = idx / TW, q = idx % TW;
            int gy = min(max(ybase + r, 0), HH - 1);
            int gx = min(max(xbase + q, 0), WW - 1);
            int g = gy * WW + gx;
            tileP[r][q] = pack2(__ldg(p0 + g), __ldg(p1 + g));
            tile2[r][q] = __ldg(p2 + g);
        }
    }
    __syncthreads();

    const int j  = j0 + tx;
    const int iA = i0 + 2 * ty;            // even; iB = iA+1. Both valid or both not.
    if (j >= WO || iA >= HO) return;

    // ---- Offset conv for both pixels; each weight vector loaded ONCE ----
    u64 offA[9], offB[9];
    #pragma unroll
    for (int p = 0; p < 9; p++) { u64 bp = ldc64(540 + 2 * p); offA[p] = bp; offB[p] = bp; }

    const int lyA = 2 * ty + RPAD, lx = tx + RPAD;

    #pragma unroll
    for (int kx = 0; kx < 3; kx++) {
        u64 rp[4]; float r2[4];
        #pragma unroll
        for (int r = 0; r < 4; r++) { rp[r] = tileP[lyA + r][lx + kx]; r2[r] = tile2[lyA + r][lx + kx]; }
        #pragma unroll
        for (int ky = 0; ky < 3; ky++) {
            float2 fA = unpack2(rp[ky]);
            float2 fB = unpack2(rp[ky + 1]);
            #pragma unroll
            for (int c = 0; c < 3; c++) {
                const int jj = c * 9 + ky * 3 + kx;
                float xa = (c == 0) ? fA.x : (c == 1) ? fA.y : r2[ky];
                float xb = (c == 0) ? fB.x : (c == 1) ? fB.y : r2[ky + 1];
                u64 xa2 = rep2(xa), xb2 = rep2(xb);
                ulonglong2 v0 = ldc128(jj * 20 + 0);
                ulonglong2 v1 = ldc128(jj * 20 + 4);
                ulonglong2 v2 = ldc128(jj * 20 + 8);
                ulonglong2 v3 = ldc128(jj * 20 + 12);
                u64 p8 = ldc64(jj * 20 + 16);
                offA[0] = ffma2(xa2, v0.x, offA[0]); offB[0] = ffma2(xb2, v0.x, offB[0]);
                offA[1] = ffma2(xa2, v0.y, offA[1]); offB[1] = ffma2(xb2, v0.y, offB[1]);
                offA[2] = ffma2(xa2, v1.x, offA[2]); offB[2] = ffma2(xb2, v1.x, offB[2]);
                offA[3] = ffma2(xa2, v1.y, offA[3]); offB[3] = ffma2(xb2, v1.y, offB[3]);
                offA[4] = ffma2(xa2, v2.x, offA[4]); offB[4] = ffma2(xb2, v2.x, offB[4]);
                offA[5] = ffma2(xa2, v2.y, offA[5]); offB[5] = ffma2(xb2, v2.y, offB[5]);
                offA[6] = ffma2(xa2, v3.x, offA[6]); offB[6] = ffma2(xb2, v3.x, offB[6]);
                offA[7] = ffma2(xa2, v3.y, offA[7]); offB[7] = ffma2(xb2, v3.y, offB[7]);
                offA[8] = ffma2(xa2, p8,   offA[8]); offB[8] = ffma2(xb2, p8,   offB[8]);
            }
        }
    }

    // ---- Deformable sampling + einsum for one pixel ----
    const float fj = (float)j;
    auto deform = [&](const u64* off, float fi, float* res) {
        u64 accP0 = 0ULL, accP1 = 0ULL, accP2 = 0ULL;
        float a20 = CW[660], a21 = CW[661], a22 = CW[662];
        #pragma unroll
        for (int k = 0; k < 9; k++) {
            const int ky = k / 3, kx = k % 3;
            u64 pyx = add2(off[k], pack2(fi + (float)ky, fj + (float)kx));
            float2 q = unpack2(pyx);                      // (py, px)
            int y0 = __float2int_rd(q.x), x0 = __float2int_rd(q.y);
            float wy = q.x - (float)y0, wx = q.y - (float)x0;
            float vy0 = ((unsigned)y0       < (unsigned)HH) ? 1.f : 0.f;
            float vy1 = ((unsigned)(y0 + 1) < (unsigned)HH) ? 1.f : 0.f;
            float vx0 = ((unsigned)x0       < (unsigned)WW) ? 1.f : 0.f;
            float vx1 = ((unsigned)(x0 + 1) < (unsigned)WW) ? 1.f : 0.f;
            float a0 = (1.f - wy) * vy0, a1 = wy * vy1;
            float b0 = (1.f - wx) * vx0, b1 = wx * vx1;
            float w00 = a0 * b0, w01 = a0 * b1, w10 = a1 * b0, w11 = a1 * b1;

            int ry = y0 - ybase, rx = x0 - xbase;         // tile-local; staging clamp
            u64 gP00, gP01, gP10, gP11;                   // already border-clamps values
            float gs00, gs01, gs10, gs11;
            if (__builtin_expect(((unsigned)ry < (unsigned)(TH - 1)) &
                                 ((unsigned)rx < (unsigned)(TW - 1)), 1)) {
                gP00 = tileP[ry][rx];     gP01 = tileP[ry][rx + 1];
                gP10 = tileP[ry + 1][rx]; gP11 = tileP[ry + 1][rx + 1];
                gs00 = tile2[ry][rx];     gs01 = tile2[ry][rx + 1];
                gs10 = tile2[ry + 1][rx]; gs11 = tile2[ry + 1][rx + 1];
            } else {
                int yc0 = min(max(y0, 0), HH - 1), yc1 = min(max(y0 + 1, 0), HH - 1);
                int xc0 = min(max(x0, 0), WW - 1), xc1 = min(max(x0 + 1, 0), WW - 1);
                int i00 = yc0 * WW + xc0, i01 = yc0 * WW + xc1;
                int i10 = yc1 * WW + xc0, i11 = yc1 * WW + xc1;
                gP00 = pack2(__ldg(p0 + i00), __ldg(p1 + i00)); gs00 = __ldg(p2 + i00);
                gP01 = pack2(__ldg(p0 + i01), __ldg(p1 + i01)); gs01 = __ldg(p2 + i01);
                gP10 = pack2(__ldg(p0 + i10), __ldg(p1 + i10)); gs10 = __ldg(p2 + i10);
                gP11 = pack2(__ldg(p0 + i11), __ldg(p1 + i11)); gs11 = __ldg(p2 + i11);
            }

            u64 v01 = mul2(gP00, rep2(w00));
            v01 = ffma2(gP01, rep2(w01), v01);
            v01 = ffma2(gP10, rep2(w10), v01);
            v01 = ffma2(gP11, rep2(w11), v01);
            float v2 = fmaf(gs11, w11, fmaf(gs10, w10, fmaf(gs01, w01, gs00 * w00)));

            ulonglong2 wp01 = ldc128(560 + k * 8);        // (o=0 pair, o=1 pair)
            u64 wp2 = ldc64(560 + k * 8 + 4);             // o=2 pair
            accP0 = ffma2(v01, wp01.x, accP0);
            accP1 = ffma2(v01, wp01.y, accP1);
            accP2 = ffma2(v01, wp2,   accP2);
            a20 = fmaf(v2, CW[632 + k * 3 + 0], a20);
            a21 = fmaf(v2, CW[632 + k * 3 + 1], a21);
            a22 = fmaf(v2, CW[632 + k * 3 + 2], a22);
        }
        float2 r0 = unpack2(accP0), r1 = unpack2(accP1), r2 = unpack2(accP2);
        res[0] = r0.x + r0.y + a20;
        res[1] = r1.x + r1.y + a21;
        res[2] = r2.x + r2.y + a22;
    };

    float rA[3], rB[3];
    deform(offA, (float)iA,        rA);
    deform(offB, (float)iA + 1.f,  rB);

    const size_t plane = (size_t)HO * WO;
    size_t pa = (size_t)b * 3 * plane + (size_t)iA * WO + j;
    out[pa]             = rA[0];
    out[pa + plane]     = rA[1];
    out[pa + 2 * plane] = rA[2];
    pa += WO;
    out[pa]             = rB[0];
    out[pa + plane]     = rB[1];
    out[pa + 2 * plane] = rB[2];
}

extern "C" void kernel_launch(void* const* d_in, const int* in_sizes, int n_in,
                              void* d_out, int out_size)
{
    const float* x      = (const float*)d_in[0];
    const float* conv_w = (const float*)d_in[1];
    const float* conv_b = (const float*)d_in[2];
    const float* dcn_w  = (const float*)d_in[3];
    const float* dcn_b  = (const float*)d_in[4];
    float* out = (float*)d_out;

    float* sp = nullptr;  void* cp = nullptr;
    cudaGetSymbolAddress((void**)&sp, d_scratch);
    cudaGetSymbolAddress(&cp, CW);

    repack<<<1, 544>>>(conv_w, conv_b, dcn_w, dcn_b, sp);
    cudaMemcpyAsync(cp, sp, 672 * sizeof(float), cudaMemcpyDeviceToDevice);

    dim3 blk(32, 4);
    dim3 grd((WO + 31) / 32, (HO + 7) / 8, 16);
    dcn_fused<<<grd, blk>>>(x, out);
}